// round 11
// baseline (speedup 1.0000x reference)
#include <cuda_runtime.h>

#define NNODES 50000
#define NEDGES 1600000
#define PGRID  296           // persistent grid for k_edge: 148 SMs x 2 blocks
#define GGRID  444           // persistent grid for k_gemm: 148 SMs x 3 blocks

// ---------------- scratch (no allocations allowed) ----------------
__device__ float g_u [NNODES * 128];
__device__ float g_s [NNODES * 128];
__device__ float g_h1[NNODES * 128];
__device__ float g_h2[NNODES * 128];
__device__ float g_p [NNODES * 128];
__device__ float g_q [NNODES * 128];
__device__ int   g_cnt[NNODES];
__device__ float g_inv[NNODES];

// ---------------- packed f32x2 helpers ----------------
__device__ __forceinline__ unsigned long long fma2(unsigned long long a,
                                                   unsigned long long b,
                                                   unsigned long long c) {
    unsigned long long d;
    asm("fma.rn.f32x2 %0, %1, %2, %3;" : "=l"(d) : "l"(a), "l"(b), "l"(c));
    return d;
}
__device__ __forceinline__ unsigned long long pack2(float x, float y) {
    unsigned long long d;
    asm("mov.b64 %0, {%1, %2};" : "=l"(d) : "f"(x), "f"(y));
    return d;
}
__device__ __forceinline__ float2 unpack2(unsigned long long v) {
    float2 r;
    asm("mov.b64 {%0, %1}, %2;" : "=f"(r.x), "=f"(r.y) : "l"(v));
    return r;
}

// ---------------- tiny utility kernels ----------------
__global__ void k_zero_cnt() {
    int i = blockIdx.x * blockDim.x + threadIdx.x;
    if (i < NNODES) g_cnt[i] = 0;
}
__global__ void k_count(const int* __restrict__ dst) {
    int e = blockIdx.x * blockDim.x + threadIdx.x;          // exactly NEDGES threads
    atomicAdd(&g_cnt[dst[e]], 1);
}
__global__ void k_inv() {
    int i = blockIdx.x * blockDim.x + threadIdx.x;
    if (i < NNODES) g_inv[i] = 1.0f / fmaxf((float)g_cnt[i], 1.0f);
}
__global__ void k_zero_f4(float* __restrict__ ptr) {
    int i = blockIdx.x * blockDim.x + threadIdx.x;          // exactly N*128/4 threads
    reinterpret_cast<float4*>(ptr)[i] = make_float4(0.f, 0.f, 0.f, 0.f);
}

// ---------------- node GEMM (persistent, 64-row tiles) ----------------------
// C = act([A1 | A2*rowscale] @ W + bias). lane -> 4 cols, warp -> 8 rows.
// 782 tiles over 444 blocks (3/SM): balanced waves.
__global__ void __launch_bounds__(256, 3)
k_gemm(const float* __restrict__ A1, int K1,
       const float* __restrict__ A2, int K2, int scaleA2,
       const float* __restrict__ W, const float* __restrict__ bias,
       float* __restrict__ C, int doRelu, int ntiles)
{
    __shared__ float Ash[32][68];                    // [k][row]
    __shared__ float Wsh[32][132];                   // [k][col]

    const int tid  = threadIdx.x;
    const int lane = tid & 31;
    const int wp   = tid >> 5;
    const int col0 = lane << 2;
    const int row0 = wp << 3;
    const int Ktot = K1 + K2;

    for (int t = blockIdx.x; t < ntiles; t += gridDim.x) {
        const int n0 = t * 64;

        unsigned long long acc[4][4];
        #pragma unroll
        for (int i = 0; i < 4; ++i)
            #pragma unroll
            for (int c = 0; c < 4; ++c) acc[i][c] = 0ull;

        for (int kb = 0; kb < Ktot; kb += 32) {
            #pragma unroll
            for (int l = 0; l < 2; ++l) {
                int i   = tid + l * 256;             // 0..511
                int row = i >> 3;
                int q   = i & 7;
                int gn  = n0 + row;
                int gk  = kb + q * 4;
                float4 f = make_float4(0.f, 0.f, 0.f, 0.f);
                if (gn < NNODES) {
                    if (gk < K1) f = *reinterpret_cast<const float4*>(&A1[(size_t)gn * K1 + gk]);
                    else {
                        f = *reinterpret_cast<const float4*>(&A2[(size_t)gn * K2 + (gk - K1)]);
                        if (scaleA2) {
                            float iv = g_inv[gn];
                            f.x *= iv; f.y *= iv; f.z *= iv; f.w *= iv;
                        }
                    }
                }
                int kk = q * 4;
                Ash[kk + 0][row] = f.x;
                Ash[kk + 1][row] = f.y;
                Ash[kk + 2][row] = f.z;
                Ash[kk + 3][row] = f.w;
            }
            #pragma unroll
            for (int l = 0; l < 4; ++l) {
                int i = tid + l * 256;
                int k = i >> 5, q = i & 31;
                float4 f = *reinterpret_cast<const float4*>(&W[(size_t)(kb + k) * 128 + q * 4]);
                *reinterpret_cast<float4*>(&Wsh[k][q * 4]) = f;
            }
            __syncthreads();

            #pragma unroll 8
            for (int k = 0; k < 32; ++k) {
                ulonglong2 a01 = *reinterpret_cast<const ulonglong2*>(&Ash[k][row0]);
                ulonglong2 a23 = *reinterpret_cast<const ulonglong2*>(&Ash[k][row0 + 4]);
                unsigned long long ap[4] = { a01.x, a01.y, a23.x, a23.y };
                float4 wv = *reinterpret_cast<const float4*>(&Wsh[k][col0]);
                unsigned long long wd[4] = { pack2(wv.x, wv.x), pack2(wv.y, wv.y),
                                             pack2(wv.z, wv.z), pack2(wv.w, wv.w) };
                #pragma unroll
                for (int r = 0; r < 4; ++r) {
                    acc[r][0] = fma2(ap[r], wd[0], acc[r][0]);
                    acc[r][1] = fma2(ap[r], wd[1], acc[r][1]);
                    acc[r][2] = fma2(ap[r], wd[2], acc[r][2]);
                    acc[r][3] = fma2(ap[r], wd[3], acc[r][3]);
                }
            }
            __syncthreads();
        }

        float bv[4];
        #pragma unroll
        for (int c = 0; c < 4; ++c) bv[c] = bias ? bias[col0 + c] : 0.f;

        #pragma unroll
        for (int rp = 0; rp < 4; ++rp) {
            float2 a0 = unpack2(acc[rp][0]);
            float2 a1 = unpack2(acc[rp][1]);
            float2 a2 = unpack2(acc[rp][2]);
            float2 a3 = unpack2(acc[rp][3]);
            #pragma unroll
            for (int h = 0; h < 2; ++h) {
                int gn = n0 + row0 + rp * 2 + h;
                if (gn >= NNODES) continue;
                float o0 = (h ? a0.y : a0.x) + bv[0];
                float o1 = (h ? a1.y : a1.x) + bv[1];
                float o2 = (h ? a2.y : a2.x) + bv[2];
                float o3 = (h ? a3.y : a3.x) + bv[3];
                if (doRelu) {
                    o0 = fmaxf(o0, 0.f); o1 = fmaxf(o1, 0.f);
                    o2 = fmaxf(o2, 0.f); o3 = fmaxf(o3, 0.f);
                }
                *reinterpret_cast<float4*>(&C[(size_t)gn * 128 + col0]) =
                    make_float4(o0, o1, o2, o3);
            }
        }
    }
}

// ---------------- dense edge GEMM + fused aggregate (persistent, 2-buffered)
// 128-edge x 128-col tiles; We staged once; Ash double-buffered with XOR
// swizzle (conflict-free transpose stores, 48KB static smem total).
__global__ void __launch_bounds__(256, 2)
k_edge(const float* __restrict__ efeats, const int* __restrict__ src,
       const int* __restrict__ dst, const float* __restrict__ We,
       const float* __restrict__ u, float* __restrict__ s)
{
    __shared__ float Ash[2][32 * 128];               // swizzled [k][row]
    __shared__ float Wsh[32 * 128];                  // [k][col]

    const int tid  = threadIdx.x;
    const int lane = tid & 31;
    const int wp   = tid >> 5;
    const int col0 = lane << 2;
    const int row0 = wp << 4;
    const int bb   = wp << 2;                        // row block base = row0>>2
    const int NT   = NEDGES / 128;                   // 12500 tiles

    // stage We once (reused across all tiles)
    #pragma unroll
    for (int l = 0; l < 4; ++l) {
        int i = tid + l * 256;
        int k = i >> 5, q = i & 31;
        float4 f = *reinterpret_cast<const float4*>(&We[(size_t)k * 128 + q * 4]);
        *reinterpret_cast<float4*>(&Wsh[k * 128 + q * 4]) = f;
    }

    // prologue: stage first tile into buffer 0
    {
        const int e0 = blockIdx.x * 128;
        #pragma unroll
        for (int l = 0; l < 4; ++l) {
            int i   = tid + l * 256;
            int row = i >> 3;
            int q   = i & 7;                         // swizzle index = q
            float4 f = reinterpret_cast<const float4*>(efeats)[(size_t)(e0 + row) * 8 + q];
            int base = ((row >> 2) ^ q) * 4 + (row & 3);
            Ash[0][(q * 4 + 0) * 128 + base] = f.x;
            Ash[0][(q * 4 + 1) * 128 + base] = f.y;
            Ash[0][(q * 4 + 2) * 128 + base] = f.z;
            Ash[0][(q * 4 + 3) * 128 + base] = f.w;
        }
    }

    int buf = 0;
    for (int t = blockIdx.x; t < NT; t += gridDim.x) {
        __syncthreads();                              // buf staged; buf^1 free

        // stage NEXT tile into buf^1 (overlaps with compute below)
        int tn = t + gridDim.x;
        if (tn < NT) {
            const int e0n = tn * 128;
            float* ab = Ash[buf ^ 1];
            #pragma unroll
            for (int l = 0; l < 4; ++l) {
                int i   = tid + l * 256;
                int row = i >> 3;
                int q   = i & 7;
                float4 f = reinterpret_cast<const float4*>(efeats)[(size_t)(e0n + row) * 8 + q];
                int base = ((row >> 2) ^ q) * 4 + (row & 3);
                ab[(q * 4 + 0) * 128 + base] = f.x;
                ab[(q * 4 + 1) * 128 + base] = f.y;
                ab[(q * 4 + 2) * 128 + base] = f.z;
                ab[(q * 4 + 3) * 128 + base] = f.w;
            }
        }

        // compute current tile
        const int e0 = t * 128;
        const float* cb = Ash[buf];

        unsigned long long acc[8][4];
        #pragma unroll
        for (int i = 0; i < 8; ++i)
            #pragma unroll
            for (int c = 0; c < 4; ++c) acc[i][c] = 0ull;

        #pragma unroll 8
        for (int k = 0; k < 32; ++k) {
            const int sw = (k >> 2) & 7;
            const float* ar = cb + k * 128;
            ulonglong2 a01 = *reinterpret_cast<const ulonglong2*>(ar + (((bb + 0) ^ sw) << 2));
            ulonglong2 a23 = *reinterpret_cast<const ulonglong2*>(ar + (((bb + 1) ^ sw) << 2));
            ulonglong2 a45 = *reinterpret_cast<const ulonglong2*>(ar + (((bb + 2) ^ sw) << 2));
            ulonglong2 a67 = *reinterpret_cast<const ulonglong2*>(ar + (((bb + 3) ^ sw) << 2));
            unsigned long long ap[8] = { a01.x, a01.y, a23.x, a23.y,
                                         a45.x, a45.y, a67.x, a67.y };
            float4 wv = *reinterpret_cast<const float4*>(&Wsh[k * 128 + col0]);
            unsigned long long wd[4] = { pack2(wv.x, wv.x), pack2(wv.y, wv.y),
                                         pack2(wv.z, wv.z), pack2(wv.w, wv.w) };
            #pragma unroll
            for (int r = 0; r < 8; ++r) {
                acc[r][0] = fma2(ap[r], wd[0], acc[r][0]);
                acc[r][1] = fma2(ap[r], wd[1], acc[r][1]);
                acc[r][2] = fma2(ap[r], wd[2], acc[r][2]);
                acc[r][3] = fma2(ap[r], wd[3], acc[r][3]);
            }
        }

        // epilogue: m = relu(u[src] + c); red-add 16B per lane into s[dst]
        #pragma unroll
        for (int rp = 0; rp < 8; ++rp) {
            float2 a0 = unpack2(acc[rp][0]);
            float2 a1 = unpack2(acc[rp][1]);
            float2 a2 = unpack2(acc[rp][2]);
            float2 a3 = unpack2(acc[rp][3]);
            #pragma unroll
            for (int h = 0; h < 2; ++h) {
                int e  = e0 + row0 + rp * 2 + h;
                int sn = __ldg(&src[e]);
                int dn = __ldg(&dst[e]);
                float4 uu = *reinterpret_cast<const float4*>(&u[(size_t)sn * 128 + col0]);
                float m0 = fmaxf(uu.x + (h ? a0.y : a0.x), 0.f);
                float m1 = fmaxf(uu.y + (h ? a1.y : a1.x), 0.f);
                float m2 = fmaxf(uu.z + (h ? a2.y : a2.x), 0.f);
                float m3 = fmaxf(uu.w + (h ? a3.y : a3.x), 0.f);
                float* sp = &s[(size_t)dn * 128 + col0];
                asm volatile("red.global.add.v4.f32 [%0], {%1, %2, %3, %4};"
                             :: "l"(sp), "f"(m0), "f"(m1), "f"(m2), "f"(m3) : "memory");
            }
        }
        buf ^= 1;
    }
}

// ---------------- edge predictor: 4 edges per warp ----------------
__global__ void __launch_bounds__(256)
k_pred(const int* __restrict__ src, const int* __restrict__ dst,
       const float* __restrict__ p, const float* __restrict__ q,
       const float* __restrict__ W2, const float* __restrict__ b2,
       float* __restrict__ out)
{
    const int wid   = threadIdx.x >> 5;
    const int lane  = threadIdx.x & 31;
    const int ebase = (blockIdx.x * 8 + wid) * 4;      // exact: E = 50000*32

    float2 w2[4];
    #pragma unroll
    for (int t = 0; t < 4; ++t)
        w2[t] = reinterpret_cast<const float2*>(W2)[lane * 4 + t];

    float s0[4], s1[4];
    #pragma unroll
    for (int j = 0; j < 4; ++j) {
        int e  = ebase + j;
        int sn = src[e];
        int dn = dst[e];
        float4 pp = *reinterpret_cast<const float4*>(&p[(size_t)sn * 128 + lane * 4]);
        float4 qq = *reinterpret_cast<const float4*>(&q[(size_t)dn * 128 + lane * 4]);
        float h0 = fmaxf(pp.x + qq.x, 0.f);
        float h1 = fmaxf(pp.y + qq.y, 0.f);
        float h2 = fmaxf(pp.z + qq.z, 0.f);
        float h3 = fmaxf(pp.w + qq.w, 0.f);
        s0[j] = h0 * w2[0].x + h1 * w2[1].x + h2 * w2[2].x + h3 * w2[3].x;
        s1[j] = h0 * w2[0].y + h1 * w2[1].y + h2 * w2[2].y + h3 * w2[3].y;
    }

    #pragma unroll
    for (int off = 16; off > 0; off >>= 1) {
        #pragma unroll
        for (int j = 0; j < 4; ++j) {
            s0[j] += __shfl_xor_sync(0xffffffffu, s0[j], off);
            s1[j] += __shfl_xor_sync(0xffffffffu, s1[j], off);
        }
    }
    if (lane == 0) {
        #pragma unroll
        for (int j = 0; j < 4; ++j) {
            out[2 * (size_t)(ebase + j)]     = s0[j] + b2[0];
            out[2 * (size_t)(ebase + j) + 1] = s1[j] + b2[1];
        }
    }
}

// ---------------- launch ----------------
extern "C" void kernel_launch(void* const* d_in, const int* in_sizes, int n_in,
                              void* d_out, int out_size)
{
    const float* nfeats = (const float*)d_in[0];
    const float* efeats = (const float*)d_in[1];
    const int*   src    = (const int*)  d_in[2];
    const int*   dst    = (const int*)  d_in[3];
    const float* Wm1 = (const float*)d_in[4];  const float* bm1 = (const float*)d_in[5];
    const float* Wa1 = (const float*)d_in[6];  const float* ba1 = (const float*)d_in[7];
    const float* Wm2 = (const float*)d_in[8];  const float* bm2 = (const float*)d_in[9];
    const float* Wa2 = (const float*)d_in[10]; const float* ba2 = (const float*)d_in[11];
    const float* W1  = (const float*)d_in[12]; const float* b1  = (const float*)d_in[13];
    const float* W2  = (const float*)d_in[14]; const float* b2  = (const float*)d_in[15];
    float* out = (float*)d_out;

    float *u, *s, *h1, *h2, *p, *q;
    cudaGetSymbolAddress((void**)&u,  g_u);
    cudaGetSymbolAddress((void**)&s,  g_s);
    cudaGetSymbolAddress((void**)&h1, g_h1);
    cudaGetSymbolAddress((void**)&h2, g_h2);
    cudaGetSymbolAddress((void**)&p,  g_p);
    cudaGetSymbolAddress((void**)&q,  g_q);

    const int NT = (NNODES + 63) / 64;        // 782 node tiles
    const int ZB = NNODES * 128 / 4 / 256;    // 6250 zero blocks (exact)
    const int CB = NEDGES / 256;              // 6250 count blocks (exact)
    const int NB = (NNODES + 255) / 256;      // 196

    // Order: k_edge is launch index 3 (ncu capture slot).
    k_zero_cnt<<<NB, 256>>>();                                             // 0
    k_zero_f4<<<ZB, 256>>>(s);                                             // 1
    k_gemm<<<GGRID, 256>>>(nfeats, 64, nullptr, 0, 0, Wm1, bm1, u, 0, NT); // 2
    k_edge<<<PGRID, 256>>>(efeats, src, dst, Wm1 + 64 * 128, u, s);        // 3 (captured)
    k_count<<<CB, 256>>>(dst);                                             // 4
    k_inv<<<NB, 256>>>();                                                  // 5
    k_gemm<<<GGRID, 256>>>(nfeats, 64, s, 128, 1, Wa1, ba1, h1, 1, NT);    // 6

    // ---- SAGE layer 2 ----
    k_zero_f4<<<ZB, 256>>>(s);
    k_gemm<<<GGRID, 256>>>(h1, 128, nullptr, 0, 0, Wm2, bm2, u, 0, NT);
    k_edge<<<PGRID, 256>>>(efeats, src, dst, Wm2 + 128 * 128, u, s);
    k_gemm<<<GGRID, 256>>>(h1, 128, s, 128, 1, Wa2, ba2, h2, 1, NT);

    // ---- predictor ----
    k_gemm<<<GGRID, 256>>>(h2, 128, nullptr, 0, 0, W1, b1, p, 0, NT);
    k_gemm<<<GGRID, 256>>>(h2, 128, nullptr, 0, 0, W1 + 128 * 128, nullptr, q, 0, NT);
    k_pred<<<NEDGES / 32, 256>>>(src, dst, p, q, W2, b2, out);
}

// round 12
// speedup vs baseline: 1.1466x; 1.1466x over previous
#include <cuda_runtime.h>

#define NNODES 50000
#define NEDGES 1600000
#define PGRID  296           // persistent grid: 148 SMs x 2 blocks

// ---------------- scratch (no allocations allowed) ----------------
__device__ float g_u [NNODES * 128];
__device__ float g_s [NNODES * 128];
__device__ float g_h1[NNODES * 128];
__device__ float g_h2[NNODES * 128];
__device__ float g_p [NNODES * 128];
__device__ float g_q [NNODES * 128];
__device__ int   g_cnt[NNODES];
__device__ float g_inv[NNODES];

// ---------------- packed f32x2 helpers ----------------
__device__ __forceinline__ unsigned long long fma2(unsigned long long a,
                                                   unsigned long long b,
                                                   unsigned long long c) {
    unsigned long long d;
    asm("fma.rn.f32x2 %0, %1, %2, %3;" : "=l"(d) : "l"(a), "l"(b), "l"(c));
    return d;
}
__device__ __forceinline__ unsigned long long pack2(float x, float y) {
    unsigned long long d;
    asm("mov.b64 %0, {%1, %2};" : "=l"(d) : "f"(x), "f"(y));
    return d;
}
__device__ __forceinline__ float2 unpack2(unsigned long long v) {
    float2 r;
    asm("mov.b64 {%0, %1}, %2;" : "=f"(r.x), "=f"(r.y) : "l"(v));
    return r;
}

// ---------------- tiny utility kernels ----------------
__global__ void k_zero_cnt() {
    int i = blockIdx.x * blockDim.x + threadIdx.x;
    if (i < NNODES) g_cnt[i] = 0;
}
__global__ void k_count(const int* __restrict__ dst) {
    int e = blockIdx.x * blockDim.x + threadIdx.x;          // exactly NEDGES threads
    atomicAdd(&g_cnt[dst[e]], 1);
}
__global__ void k_inv() {
    int i = blockIdx.x * blockDim.x + threadIdx.x;
    if (i < NNODES) g_inv[i] = 1.0f / fmaxf((float)g_cnt[i], 1.0f);
}
__global__ void k_zero_f4(float* __restrict__ ptr) {
    int i = blockIdx.x * blockDim.x + threadIdx.x;          // exactly N*128/4 threads
    reinterpret_cast<float4*>(ptr)[i] = make_float4(0.f, 0.f, 0.f, 0.f);
}

// ---------------- node GEMM (persistent, 128-row tiles) ---------------------
// C = act([A1 | A2*rowscale] @ W + bias). lane -> 4 cols, warp -> 16 rows.
__global__ void __launch_bounds__(256, 2)
k_gemm(const float* __restrict__ A1, int K1,
       const float* __restrict__ A2, int K2, int scaleA2,
       const float* __restrict__ W, const float* __restrict__ bias,
       float* __restrict__ C, int doRelu, int ntiles)
{
    __shared__ float Ash[32][132];                   // [k][row]
    __shared__ float Wsh[32][132];                   // [k][col]

    const int tid  = threadIdx.x;
    const int lane = tid & 31;
    const int wp   = tid >> 5;
    const int col0 = lane << 2;
    const int row0 = wp << 4;
    const int Ktot = K1 + K2;

    for (int t = blockIdx.x; t < ntiles; t += gridDim.x) {
        const int n0 = t * 128;

        unsigned long long acc[8][4];
        #pragma unroll
        for (int i = 0; i < 8; ++i)
            #pragma unroll
            for (int c = 0; c < 4; ++c) acc[i][c] = 0ull;

        for (int kb = 0; kb < Ktot; kb += 32) {
            #pragma unroll
            for (int l = 0; l < 4; ++l) {
                int i   = tid + l * 256;             // 0..1023
                int row = i >> 3;
                int q   = i & 7;
                int gn  = n0 + row;
                int gk  = kb + q * 4;
                float4 f = make_float4(0.f, 0.f, 0.f, 0.f);
                if (gn < NNODES) {
                    if (gk < K1) f = *reinterpret_cast<const float4*>(&A1[(size_t)gn * K1 + gk]);
                    else {
                        f = *reinterpret_cast<const float4*>(&A2[(size_t)gn * K2 + (gk - K1)]);
                        if (scaleA2) {
                            float iv = g_inv[gn];
                            f.x *= iv; f.y *= iv; f.z *= iv; f.w *= iv;
                        }
                    }
                }
                int kk = q * 4;
                Ash[kk + 0][row] = f.x;
                Ash[kk + 1][row] = f.y;
                Ash[kk + 2][row] = f.z;
                Ash[kk + 3][row] = f.w;
            }
            #pragma unroll
            for (int l = 0; l < 4; ++l) {
                int i = tid + l * 256;
                int k = i >> 5, q = i & 31;
                float4 f = *reinterpret_cast<const float4*>(&W[(size_t)(kb + k) * 128 + q * 4]);
                *reinterpret_cast<float4*>(&Wsh[k][q * 4]) = f;
            }
            __syncthreads();

            #pragma unroll 8
            for (int k = 0; k < 32; ++k) {
                ulonglong2 a01 = *reinterpret_cast<const ulonglong2*>(&Ash[k][row0]);
                ulonglong2 a23 = *reinterpret_cast<const ulonglong2*>(&Ash[k][row0 + 4]);
                ulonglong2 a45 = *reinterpret_cast<const ulonglong2*>(&Ash[k][row0 + 8]);
                ulonglong2 a67 = *reinterpret_cast<const ulonglong2*>(&Ash[k][row0 + 12]);
                unsigned long long ap[8] = { a01.x, a01.y, a23.x, a23.y,
                                             a45.x, a45.y, a67.x, a67.y };
                float4 wv = *reinterpret_cast<const float4*>(&Wsh[k][col0]);
                unsigned long long wd[4] = { pack2(wv.x, wv.x), pack2(wv.y, wv.y),
                                             pack2(wv.z, wv.z), pack2(wv.w, wv.w) };
                #pragma unroll
                for (int r = 0; r < 8; ++r) {
                    acc[r][0] = fma2(ap[r], wd[0], acc[r][0]);
                    acc[r][1] = fma2(ap[r], wd[1], acc[r][1]);
                    acc[r][2] = fma2(ap[r], wd[2], acc[r][2]);
                    acc[r][3] = fma2(ap[r], wd[3], acc[r][3]);
                }
            }
            __syncthreads();
        }

        float bv[4];
        #pragma unroll
        for (int c = 0; c < 4; ++c) bv[c] = bias ? bias[col0 + c] : 0.f;

        #pragma unroll
        for (int rp = 0; rp < 8; ++rp) {
            float2 a0 = unpack2(acc[rp][0]);
            float2 a1 = unpack2(acc[rp][1]);
            float2 a2 = unpack2(acc[rp][2]);
            float2 a3 = unpack2(acc[rp][3]);
            #pragma unroll
            for (int h = 0; h < 2; ++h) {
                int gn = n0 + row0 + rp * 2 + h;
                if (gn >= NNODES) continue;
                float o0 = (h ? a0.y : a0.x) + bv[0];
                float o1 = (h ? a1.y : a1.x) + bv[1];
                float o2 = (h ? a2.y : a2.x) + bv[2];
                float o3 = (h ? a3.y : a3.x) + bv[3];
                if (doRelu) {
                    o0 = fmaxf(o0, 0.f); o1 = fmaxf(o1, 0.f);
                    o2 = fmaxf(o2, 0.f); o3 = fmaxf(o3, 0.f);
                }
                *reinterpret_cast<float4*>(&C[(size_t)gn * 128 + col0]) =
                    make_float4(o0, o1, o2, o3);
            }
        }
    }
}

// ---------------- fused dual-weight GEMM: P = A@Wp + bp, Q = A@Wq ------------
// 64-row tiles, K=128 fixed. One A staging feeds both accumulator sets.
__global__ void __launch_bounds__(256, 2)
k_gemm2(const float* __restrict__ A,
        const float* __restrict__ Wp, const float* __restrict__ bp,
        const float* __restrict__ Wq,
        float* __restrict__ P, float* __restrict__ Q, int ntiles)
{
    __shared__ float Ash[32][68];                    // [k][row]
    __shared__ float Wpsh[32][132];
    __shared__ float Wqsh[32][132];

    const int tid  = threadIdx.x;
    const int lane = tid & 31;
    const int wp   = tid >> 5;
    const int col0 = lane << 2;
    const int row0 = wp << 3;                        // 8 rows per warp

    for (int t = blockIdx.x; t < ntiles; t += gridDim.x) {
        const int n0 = t * 64;

        unsigned long long ap_[4][4], aq_[4][4];
        #pragma unroll
        for (int i = 0; i < 4; ++i)
            #pragma unroll
            for (int c = 0; c < 4; ++c) { ap_[i][c] = 0ull; aq_[i][c] = 0ull; }

        for (int kb = 0; kb < 128; kb += 32) {
            #pragma unroll
            for (int l = 0; l < 2; ++l) {
                int i   = tid + l * 256;             // 0..511
                int row = i >> 3;
                int q   = i & 7;
                int gn  = n0 + row;
                float4 f = make_float4(0.f, 0.f, 0.f, 0.f);
                if (gn < NNODES)
                    f = *reinterpret_cast<const float4*>(&A[(size_t)gn * 128 + kb + q * 4]);
                int kk = q * 4;
                Ash[kk + 0][row] = f.x;
                Ash[kk + 1][row] = f.y;
                Ash[kk + 2][row] = f.z;
                Ash[kk + 3][row] = f.w;
            }
            #pragma unroll
            for (int l = 0; l < 4; ++l) {
                int i = tid + l * 256;
                int k = i >> 5, q = i & 31;
                *reinterpret_cast<float4*>(&Wpsh[k][q * 4]) =
                    *reinterpret_cast<const float4*>(&Wp[(size_t)(kb + k) * 128 + q * 4]);
                *reinterpret_cast<float4*>(&Wqsh[k][q * 4]) =
                    *reinterpret_cast<const float4*>(&Wq[(size_t)(kb + k) * 128 + q * 4]);
            }
            __syncthreads();

            #pragma unroll 8
            for (int k = 0; k < 32; ++k) {
                ulonglong2 a01 = *reinterpret_cast<const ulonglong2*>(&Ash[k][row0]);
                ulonglong2 a23 = *reinterpret_cast<const ulonglong2*>(&Ash[k][row0 + 4]);
                unsigned long long av[4] = { a01.x, a01.y, a23.x, a23.y };
                float4 wvp = *reinterpret_cast<const float4*>(&Wpsh[k][col0]);
                float4 wvq = *reinterpret_cast<const float4*>(&Wqsh[k][col0]);
                unsigned long long wdp[4] = { pack2(wvp.x, wvp.x), pack2(wvp.y, wvp.y),
                                              pack2(wvp.z, wvp.z), pack2(wvp.w, wvp.w) };
                unsigned long long wdq[4] = { pack2(wvq.x, wvq.x), pack2(wvq.y, wvq.y),
                                              pack2(wvq.z, wvq.z), pack2(wvq.w, wvq.w) };
                #pragma unroll
                for (int r = 0; r < 4; ++r) {
                    ap_[r][0] = fma2(av[r], wdp[0], ap_[r][0]);
                    ap_[r][1] = fma2(av[r], wdp[1], ap_[r][1]);
                    ap_[r][2] = fma2(av[r], wdp[2], ap_[r][2]);
                    ap_[r][3] = fma2(av[r], wdp[3], ap_[r][3]);
                    aq_[r][0] = fma2(av[r], wdq[0], aq_[r][0]);
                    aq_[r][1] = fma2(av[r], wdq[1], aq_[r][1]);
                    aq_[r][2] = fma2(av[r], wdq[2], aq_[r][2]);
                    aq_[r][3] = fma2(av[r], wdq[3], aq_[r][3]);
                }
            }
            __syncthreads();
        }

        float bv[4];
        #pragma unroll
        for (int c = 0; c < 4; ++c) bv[c] = bp[col0 + c];

        #pragma unroll
        for (int rp = 0; rp < 4; ++rp) {
            float2 p0 = unpack2(ap_[rp][0]);
            float2 p1 = unpack2(ap_[rp][1]);
            float2 p2 = unpack2(ap_[rp][2]);
            float2 p3 = unpack2(ap_[rp][3]);
            float2 q0 = unpack2(aq_[rp][0]);
            float2 q1 = unpack2(aq_[rp][1]);
            float2 q2 = unpack2(aq_[rp][2]);
            float2 q3 = unpack2(aq_[rp][3]);
            #pragma unroll
            for (int h = 0; h < 2; ++h) {
                int gn = n0 + row0 + rp * 2 + h;
                if (gn >= NNODES) continue;
                *reinterpret_cast<float4*>(&P[(size_t)gn * 128 + col0]) =
                    make_float4((h ? p0.y : p0.x) + bv[0], (h ? p1.y : p1.x) + bv[1],
                                (h ? p2.y : p2.x) + bv[2], (h ? p3.y : p3.x) + bv[3]);
                *reinterpret_cast<float4*>(&Q[(size_t)gn * 128 + col0]) =
                    make_float4(h ? q0.y : q0.x, h ? q1.y : q1.x,
                                h ? q2.y : q2.x, h ? q3.y : q3.x);
            }
        }
    }
}

// ---------------- dense edge GEMM + fused aggregate (R7 champion) -----------
// Tile: 128 edges x 128 cols, K=32. lane -> 4 cols, warp -> 16 rows.
// Epilogue: m = relu(u[src] + c), red.global.add.v4 into s[dst].
__global__ void __launch_bounds__(256, 2)
k_edge(const float* __restrict__ efeats, const int* __restrict__ src,
       const int* __restrict__ dst, const float* __restrict__ We,
       const float* __restrict__ u, float* __restrict__ s)
{
    __shared__ float Ash[32][132];
    __shared__ float Wsh[32][132];

    const int tid  = threadIdx.x;
    const int lane = tid & 31;
    const int wp   = tid >> 5;
    const int col0 = lane << 2;
    const int row0 = wp << 4;
    const int e0   = blockIdx.x * 128;               // exact: E = 12500*128

    #pragma unroll
    for (int l = 0; l < 4; ++l) {
        int i   = tid + l * 256;
        int row = i >> 3;
        int q   = i & 7;
        float4 f = reinterpret_cast<const float4*>(efeats)[(size_t)(e0 + row) * 8 + q];
        int kk = q * 4;
        Ash[kk + 0][row] = f.x;
        Ash[kk + 1][row] = f.y;
        Ash[kk + 2][row] = f.z;
        Ash[kk + 3][row] = f.w;
    }
    #pragma unroll
    for (int l = 0; l < 4; ++l) {
        int i = tid + l * 256;
        int k = i >> 5, q = i & 31;
        float4 f = *reinterpret_cast<const float4*>(&We[(size_t)k * 128 + q * 4]);
        *reinterpret_cast<float4*>(&Wsh[k][q * 4]) = f;
    }
    __syncthreads();

    unsigned long long acc[8][4];
    #pragma unroll
    for (int i = 0; i < 8; ++i)
        #pragma unroll
        for (int c = 0; c < 4; ++c) acc[i][c] = 0ull;

    #pragma unroll 8
    for (int k = 0; k < 32; ++k) {
        ulonglong2 a01 = *reinterpret_cast<const ulonglong2*>(&Ash[k][row0]);
        ulonglong2 a23 = *reinterpret_cast<const ulonglong2*>(&Ash[k][row0 + 4]);
        ulonglong2 a45 = *reinterpret_cast<const ulonglong2*>(&Ash[k][row0 + 8]);
        ulonglong2 a67 = *reinterpret_cast<const ulonglong2*>(&Ash[k][row0 + 12]);
        unsigned long long ap[8] = { a01.x, a01.y, a23.x, a23.y,
                                     a45.x, a45.y, a67.x, a67.y };
        float4 wv = *reinterpret_cast<const float4*>(&Wsh[k][col0]);
        unsigned long long wd[4] = { pack2(wv.x, wv.x), pack2(wv.y, wv.y),
                                     pack2(wv.z, wv.z), pack2(wv.w, wv.w) };
        #pragma unroll
        for (int r = 0; r < 8; ++r) {
            acc[r][0] = fma2(ap[r], wd[0], acc[r][0]);
            acc[r][1] = fma2(ap[r], wd[1], acc[r][1]);
            acc[r][2] = fma2(ap[r], wd[2], acc[r][2]);
            acc[r][3] = fma2(ap[r], wd[3], acc[r][3]);
        }
    }

    // epilogue: per row, m = relu(u[src] + c); red-add 16B per lane into s[dst]
    #pragma unroll
    for (int rp = 0; rp < 8; ++rp) {
        float2 a0 = unpack2(acc[rp][0]);
        float2 a1 = unpack2(acc[rp][1]);
        float2 a2 = unpack2(acc[rp][2]);
        float2 a3 = unpack2(acc[rp][3]);
        #pragma unroll
        for (int h = 0; h < 2; ++h) {
            int e  = e0 + row0 + rp * 2 + h;
            int sn = __ldg(&src[e]);
            int dn = __ldg(&dst[e]);
            float4 uu = *reinterpret_cast<const float4*>(&u[(size_t)sn * 128 + col0]);
            float m0 = fmaxf(uu.x + (h ? a0.y : a0.x), 0.f);
            float m1 = fmaxf(uu.y + (h ? a1.y : a1.x), 0.f);
            float m2 = fmaxf(uu.z + (h ? a2.y : a2.x), 0.f);
            float m3 = fmaxf(uu.w + (h ? a3.y : a3.x), 0.f);
            float* sp = &s[(size_t)dn * 128 + col0];
            asm volatile("red.global.add.v4.f32 [%0], {%1, %2, %3, %4};"
                         :: "l"(sp), "f"(m0), "f"(m1), "f"(m2), "f"(m3) : "memory");
        }
    }
}

// ---------------- edge predictor: 4 edges per warp ----------------
__global__ void __launch_bounds__(256)
k_pred(const int* __restrict__ src, const int* __restrict__ dst,
       const float* __restrict__ p, const float* __restrict__ q,
       const float* __restrict__ W2, const float* __restrict__ b2,
       float* __restrict__ out)
{
    const int wid   = threadIdx.x >> 5;
    const int lane  = threadIdx.x & 31;
    const int ebase = (blockIdx.x * 8 + wid) * 4;      // exact: E = 50000*32

    float2 w2[4];
    #pragma unroll
    for (int t = 0; t < 4; ++t)
        w2[t] = reinterpret_cast<const float2*>(W2)[lane * 4 + t];

    float s0[4], s1[4];
    #pragma unroll
    for (int j = 0; j < 4; ++j) {
        int e  = ebase + j;
        int sn = src[e];
        int dn = dst[e];
        float4 pp = *reinterpret_cast<const float4*>(&p[(size_t)sn * 128 + lane * 4]);
        float4 qq = *reinterpret_cast<const float4*>(&q[(size_t)dn * 128 + lane * 4]);
        float h0 = fmaxf(pp.x + qq.x, 0.f);
        float h1 = fmaxf(pp.y + qq.y, 0.f);
        float h2 = fmaxf(pp.z + qq.z, 0.f);
        float h3 = fmaxf(pp.w + qq.w, 0.f);
        s0[j] = h0 * w2[0].x + h1 * w2[1].x + h2 * w2[2].x + h3 * w2[3].x;
        s1[j] = h0 * w2[0].y + h1 * w2[1].y + h2 * w2[2].y + h3 * w2[3].y;
    }

    #pragma unroll
    for (int off = 16; off > 0; off >>= 1) {
        #pragma unroll
        for (int j = 0; j < 4; ++j) {
            s0[j] += __shfl_xor_sync(0xffffffffu, s0[j], off);
            s1[j] += __shfl_xor_sync(0xffffffffu, s1[j], off);
        }
    }
    if (lane == 0) {
        #pragma unroll
        for (int j = 0; j < 4; ++j) {
            out[2 * (size_t)(ebase + j)]     = s0[j] + b2[0];
            out[2 * (size_t)(ebase + j) + 1] = s1[j] + b2[1];
        }
    }
}

// ---------------- launch ----------------
extern "C" void kernel_launch(void* const* d_in, const int* in_sizes, int n_in,
                              void* d_out, int out_size)
{
    const float* nfeats = (const float*)d_in[0];
    const float* efeats = (const float*)d_in[1];
    const int*   src    = (const int*)  d_in[2];
    const int*   dst    = (const int*)  d_in[3];
    const float* Wm1 = (const float*)d_in[4];  const float* bm1 = (const float*)d_in[5];
    const float* Wa1 = (const float*)d_in[6];  const float* ba1 = (const float*)d_in[7];
    const float* Wm2 = (const float*)d_in[8];  const float* bm2 = (const float*)d_in[9];
    const float* Wa2 = (const float*)d_in[10]; const float* ba2 = (const float*)d_in[11];
    const float* W1  = (const float*)d_in[12]; const float* b1  = (const float*)d_in[13];
    const float* W2  = (const float*)d_in[14]; const float* b2  = (const float*)d_in[15];
    float* out = (float*)d_out;

    float *u, *s, *h1, *h2, *p, *q;
    cudaGetSymbolAddress((void**)&u,  g_u);
    cudaGetSymbolAddress((void**)&s,  g_s);
    cudaGetSymbolAddress((void**)&h1, g_h1);
    cudaGetSymbolAddress((void**)&h2, g_h2);
    cudaGetSymbolAddress((void**)&p,  g_p);
    cudaGetSymbolAddress((void**)&q,  g_q);

    const int NT  = (NNODES + 127) / 128;     // 391 node tiles (k_gemm)
    const int NT2 = (NNODES + 63) / 64;       // 782 node tiles (k_gemm2)
    const int ZB  = NNODES * 128 / 4 / 256;   // 6250 zero blocks (exact)
    const int EB  = NEDGES / 128;             // 12500 edge-gemm blocks (exact)
    const int CB  = NEDGES / 256;             // 6250 count blocks (exact)
    const int NB  = (NNODES + 255) / 256;     // 196

    // Order: k_edge is launch index 3 (ncu capture slot).
    k_zero_cnt<<<NB, 256>>>();                                             // 0
    k_zero_f4<<<ZB, 256>>>(s);                                             // 1
    k_gemm<<<PGRID, 256>>>(nfeats, 64, nullptr, 0, 0, Wm1, bm1, u, 0, NT); // 2
    k_edge<<<EB, 256>>>(efeats, src, dst, Wm1 + 64 * 128, u, s);           // 3 (captured)
    k_count<<<CB, 256>>>(dst);                                             // 4
    k_inv<<<NB, 256>>>();                                                  // 5
    k_gemm<<<PGRID, 256>>>(nfeats, 64, s, 128, 1, Wa1, ba1, h1, 1, NT);    // 6

    // ---- SAGE layer 2 ----
    k_zero_f4<<<ZB, 256>>>(s);
    k_gemm<<<PGRID, 256>>>(h1, 128, nullptr, 0, 0, Wm2, bm2, u, 0, NT);
    k_edge<<<EB, 256>>>(efeats, src, dst, Wm2 + 128 * 128, u, s);
    k_gemm<<<PGRID, 256>>>(h1, 128, s, 128, 1, Wa2, ba2, h2, 1, NT);

    // ---- predictor (p and q fused into one pass over h2) ----
    k_gemm2<<<PGRID, 256>>>(h2, W1, b1, W1 + 128 * 128, p, q, NT2);
    k_pred<<<NEDGES / 32, 256>>>(src, dst, p, q, W2, b2, out);
}

// round 13
// speedup vs baseline: 1.1746x; 1.0245x over previous
#include <cuda_runtime.h>

#define NNODES 50000
#define NEDGES 1600000
#define PGRID  296           // persistent grid: 148 SMs x 2 blocks

// ---------------- scratch (no allocations allowed) ----------------
__device__ float g_u [NNODES * 128];
__device__ float g_s [NNODES * 128];
__device__ float g_h1[NNODES * 128];
__device__ float g_h2[NNODES * 128];
__device__ float g_p [NNODES * 128];
__device__ float g_q [NNODES * 128];
__device__ int   g_cnt[NNODES];
__device__ float g_inv[NNODES];

// ---------------- packed f32x2 helpers ----------------
__device__ __forceinline__ unsigned long long fma2(unsigned long long a,
                                                   unsigned long long b,
                                                   unsigned long long c) {
    unsigned long long d;
    asm("fma.rn.f32x2 %0, %1, %2, %3;" : "=l"(d) : "l"(a), "l"(b), "l"(c));
    return d;
}
__device__ __forceinline__ unsigned long long pack2(float x, float y) {
    unsigned long long d;
    asm("mov.b64 %0, {%1, %2};" : "=l"(d) : "f"(x), "f"(y));
    return d;
}
__device__ __forceinline__ float2 unpack2(unsigned long long v) {
    float2 r;
    asm("mov.b64 {%0, %1}, %2;" : "=f"(r.x), "=f"(r.y) : "l"(v));
    return r;
}

// ---------------- utility kernels ----------------
__global__ void k_init(float* __restrict__ s) {          // zero s + cnt
    int i = blockIdx.x * blockDim.x + threadIdx.x;       // N*128/4 threads
    reinterpret_cast<float4*>(s)[i] = make_float4(0.f, 0.f, 0.f, 0.f);
    if (i < NNODES) g_cnt[i] = 0;
}
__global__ void k_count(const int* __restrict__ dst) {
    int e = blockIdx.x * blockDim.x + threadIdx.x;       // exactly NEDGES threads
    atomicAdd(&g_cnt[dst[e]], 1);
}
__global__ void k_inv() {
    int i = blockIdx.x * blockDim.x + threadIdx.x;
    if (i < NNODES) g_inv[i] = 1.0f / fmaxf((float)g_cnt[i], 1.0f);
}
__global__ void k_zero_f4(float* __restrict__ ptr) {
    int i = blockIdx.x * blockDim.x + threadIdx.x;       // exactly N*128/4 threads
    reinterpret_cast<float4*>(ptr)[i] = make_float4(0.f, 0.f, 0.f, 0.f);
}

// ---------------- GEMM tile primitives (device inline) ----------------------
// 128-row x 128-col tile, 256 threads; lane -> 4 cols, warp -> 16 rows.

struct GemmCtx {
    int tid, lane, wp, col0, row0;
};

// stage A block [k][row] from [A1 | A2*rowscale], guarded
__device__ __forceinline__ void stage_A(float (*Ash)[132], const GemmCtx& g, int n0,
                                        const float* A1, int K1,
                                        const float* A2, int K2, int scaleA2, int kb)
{
    #pragma unroll
    for (int l = 0; l < 4; ++l) {
        int i   = g.tid + l * 256;                 // 0..1023
        int row = i >> 3;
        int q   = i & 7;
        int gn  = n0 + row;
        int gk  = kb + q * 4;
        float4 f = make_float4(0.f, 0.f, 0.f, 0.f);
        if (gn < NNODES) {
            if (gk < K1) f = *reinterpret_cast<const float4*>(&A1[(size_t)gn * K1 + gk]);
            else {
                f = *reinterpret_cast<const float4*>(&A2[(size_t)gn * K2 + (gk - K1)]);
                if (scaleA2) {
                    float iv = g_inv[gn];
                    f.x *= iv; f.y *= iv; f.z *= iv; f.w *= iv;
                }
            }
        }
        int kk = q * 4;
        Ash[kk + 0][row] = f.x;
        Ash[kk + 1][row] = f.y;
        Ash[kk + 2][row] = f.z;
        Ash[kk + 3][row] = f.w;
    }
}

__device__ __forceinline__ void stage_W(float (*Wsh)[132], const GemmCtx& g,
                                        const float* W, int kb)
{
    #pragma unroll
    for (int l = 0; l < 4; ++l) {
        int i = g.tid + l * 256;
        int k = i >> 5, q = i & 31;
        float4 f = *reinterpret_cast<const float4*>(&W[(size_t)(kb + k) * 128 + q * 4]);
        *reinterpret_cast<float4*>(&Wsh[k][q * 4]) = f;
    }
}

__device__ __forceinline__ void mma_block(const float (*Ash)[132], const float (*Wsh)[132],
                                          const GemmCtx& g, unsigned long long acc[8][4])
{
    #pragma unroll 8
    for (int k = 0; k < 32; ++k) {
        ulonglong2 a01 = *reinterpret_cast<const ulonglong2*>(&Ash[k][g.row0]);
        ulonglong2 a23 = *reinterpret_cast<const ulonglong2*>(&Ash[k][g.row0 + 4]);
        ulonglong2 a45 = *reinterpret_cast<const ulonglong2*>(&Ash[k][g.row0 + 8]);
        ulonglong2 a67 = *reinterpret_cast<const ulonglong2*>(&Ash[k][g.row0 + 12]);
        unsigned long long ap[8] = { a01.x, a01.y, a23.x, a23.y,
                                     a45.x, a45.y, a67.x, a67.y };
        float4 wv = *reinterpret_cast<const float4*>(&Wsh[k][g.col0]);
        unsigned long long wd[4] = { pack2(wv.x, wv.x), pack2(wv.y, wv.y),
                                     pack2(wv.z, wv.z), pack2(wv.w, wv.w) };
        #pragma unroll
        for (int r = 0; r < 8; ++r) {
            acc[r][0] = fma2(ap[r], wd[0], acc[r][0]);
            acc[r][1] = fma2(ap[r], wd[1], acc[r][1]);
            acc[r][2] = fma2(ap[r], wd[2], acc[r][2]);
            acc[r][3] = fma2(ap[r], wd[3], acc[r][3]);
        }
    }
}

__device__ __forceinline__ void store_C(const GemmCtx& g, int n0,
                                        unsigned long long acc[8][4],
                                        const float* bias, float* C, int doRelu)
{
    float bv[4];
    #pragma unroll
    for (int c = 0; c < 4; ++c) bv[c] = bias ? bias[g.col0 + c] : 0.f;

    #pragma unroll
    for (int rp = 0; rp < 8; ++rp) {
        float2 a0 = unpack2(acc[rp][0]);
        float2 a1 = unpack2(acc[rp][1]);
        float2 a2 = unpack2(acc[rp][2]);
        float2 a3 = unpack2(acc[rp][3]);
        #pragma unroll
        for (int h = 0; h < 2; ++h) {
            int gn = n0 + g.row0 + rp * 2 + h;
            if (gn >= NNODES) continue;
            float o0 = (h ? a0.y : a0.x) + bv[0];
            float o1 = (h ? a1.y : a1.x) + bv[1];
            float o2 = (h ? a2.y : a2.x) + bv[2];
            float o3 = (h ? a3.y : a3.x) + bv[3];
            if (doRelu) {
                o0 = fmaxf(o0, 0.f); o1 = fmaxf(o1, 0.f);
                o2 = fmaxf(o2, 0.f); o3 = fmaxf(o3, 0.f);
            }
            *reinterpret_cast<float4*>(&C[(size_t)gn * 128 + g.col0]) =
                make_float4(o0, o1, o2, o3);
        }
    }
}

// ---------------- node GEMM (persistent) ------------------------------------
__global__ void __launch_bounds__(256, 2)
k_gemm(const float* __restrict__ A1, int K1,
       const float* __restrict__ A2, int K2, int scaleA2,
       const float* __restrict__ W, const float* __restrict__ bias,
       float* __restrict__ C, int doRelu, int ntiles)
{
    __shared__ float Ash[32][132];
    __shared__ float Wsh[32][132];

    GemmCtx g;
    g.tid  = threadIdx.x;
    g.lane = g.tid & 31;
    g.wp   = g.tid >> 5;
    g.col0 = g.lane << 2;
    g.row0 = g.wp << 4;
    const int Ktot = K1 + K2;

    for (int t = blockIdx.x; t < ntiles; t += gridDim.x) {
        const int n0 = t * 128;
        unsigned long long acc[8][4];
        #pragma unroll
        for (int i = 0; i < 8; ++i)
            #pragma unroll
            for (int c = 0; c < 4; ++c) acc[i][c] = 0ull;

        for (int kb = 0; kb < Ktot; kb += 32) {
            stage_A(Ash, g, n0, A1, K1, A2, K2, scaleA2, kb);
            stage_W(Wsh, g, W, kb);
            __syncthreads();
            mma_block(Ash, Wsh, g, acc);
            __syncthreads();
        }
        store_C(g, n0, acc, bias, C, doRelu);
    }
}

// ---------------- chained GEMM (persistent) ---------------------------------
// Phase 1: C1 = relu([A1 | A2*inv] @ Wa + ba)   (K1+K2)
// Phase 2: for j in outputs: Cj = C1 @ Wj (+bj)  (K=128, row-local chaining)
__global__ void __launch_bounds__(256, 2)
k_chain(const float* __restrict__ A1, int K1,
        const float* __restrict__ A2, int K2, int scaleA2,
        const float* __restrict__ Wa, const float* __restrict__ ba,
        float* __restrict__ C1,
        const float* __restrict__ Wb, const float* __restrict__ bb,
        float* __restrict__ Cb,
        const float* __restrict__ Wc, float* __restrict__ Cc,
        int ntiles)
{
    __shared__ float Ash[32][132];
    __shared__ float Wsh[32][132];

    GemmCtx g;
    g.tid  = threadIdx.x;
    g.lane = g.tid & 31;
    g.wp   = g.tid >> 5;
    g.col0 = g.lane << 2;
    g.row0 = g.wp << 4;
    const int Ktot = K1 + K2;

    for (int t = blockIdx.x; t < ntiles; t += gridDim.x) {
        const int n0 = t * 128;

        // ---- phase 1 ----
        {
            unsigned long long acc[8][4];
            #pragma unroll
            for (int i = 0; i < 8; ++i)
                #pragma unroll
                for (int c = 0; c < 4; ++c) acc[i][c] = 0ull;

            for (int kb = 0; kb < Ktot; kb += 32) {
                stage_A(Ash, g, n0, A1, K1, A2, K2, scaleA2, kb);
                stage_W(Wsh, g, Wa, kb);
                __syncthreads();
                mma_block(Ash, Wsh, g, acc);
                __syncthreads();
            }
            store_C(g, n0, acc, ba, C1, 1);
        }
        __syncthreads();   // C1 tile visible to whole block

        // ---- phase 2: chained outputs read C1 tile (L1-hot) ----
        #pragma unroll 1
        for (int j = 0; j < 2; ++j) {
            const float* Wj = (j == 0) ? Wb : Wc;
            float*       Cj = (j == 0) ? Cb : Cc;
            if (!Wj) break;
            const float* bj = (j == 0) ? bb : nullptr;

            unsigned long long acc[8][4];
            #pragma unroll
            for (int i = 0; i < 8; ++i)
                #pragma unroll
                for (int c = 0; c < 4; ++c) acc[i][c] = 0ull;

            for (int kb = 0; kb < 128; kb += 32) {
                stage_A(Ash, g, n0, C1, 128, nullptr, 0, 0, kb);
                stage_W(Wsh, g, Wj, kb);
                __syncthreads();
                mma_block(Ash, Wsh, g, acc);
                __syncthreads();
            }
            store_C(g, n0, acc, bj, Cj, 0);
        }
    }
}

// ---------------- dense edge GEMM + fused aggregate (R7 champion) -----------
__global__ void __launch_bounds__(256, 2)
k_edge(const float* __restrict__ efeats, const int* __restrict__ src,
       const int* __restrict__ dst, const float* __restrict__ We,
       const float* __restrict__ u, float* __restrict__ s)
{
    __shared__ float Ash[32][132];
    __shared__ float Wsh[32][132];

    const int tid  = threadIdx.x;
    const int lane = tid & 31;
    const int wp   = tid >> 5;
    const int col0 = lane << 2;
    const int row0 = wp << 4;
    const int e0   = blockIdx.x * 128;               // exact: E = 12500*128

    #pragma unroll
    for (int l = 0; l < 4; ++l) {
        int i   = tid + l * 256;
        int row = i >> 3;
        int q   = i & 7;
        float4 f = reinterpret_cast<const float4*>(efeats)[(size_t)(e0 + row) * 8 + q];
        int kk = q * 4;
        Ash[kk + 0][row] = f.x;
        Ash[kk + 1][row] = f.y;
        Ash[kk + 2][row] = f.z;
        Ash[kk + 3][row] = f.w;
    }
    #pragma unroll
    for (int l = 0; l < 4; ++l) {
        int i = tid + l * 256;
        int k = i >> 5, q = i & 31;
        float4 f = *reinterpret_cast<const float4*>(&We[(size_t)k * 128 + q * 4]);
        *reinterpret_cast<float4*>(&Wsh[k][q * 4]) = f;
    }
    __syncthreads();

    unsigned long long acc[8][4];
    #pragma unroll
    for (int i = 0; i < 8; ++i)
        #pragma unroll
        for (int c = 0; c < 4; ++c) acc[i][c] = 0ull;

    #pragma unroll 8
    for (int k = 0; k < 32; ++k) {
        ulonglong2 a01 = *reinterpret_cast<const ulonglong2*>(&Ash[k][row0]);
        ulonglong2 a23 = *reinterpret_cast<const ulonglong2*>(&Ash[k][row0 + 4]);
        ulonglong2 a45 = *reinterpret_cast<const ulonglong2*>(&Ash[k][row0 + 8]);
        ulonglong2 a67 = *reinterpret_cast<const ulonglong2*>(&Ash[k][row0 + 12]);
        unsigned long long ap[8] = { a01.x, a01.y, a23.x, a23.y,
                                     a45.x, a45.y, a67.x, a67.y };
        float4 wv = *reinterpret_cast<const float4*>(&Wsh[k][col0]);
        unsigned long long wd[4] = { pack2(wv.x, wv.x), pack2(wv.y, wv.y),
                                     pack2(wv.z, wv.z), pack2(wv.w, wv.w) };
        #pragma unroll
        for (int r = 0; r < 8; ++r) {
            acc[r][0] = fma2(ap[r], wd[0], acc[r][0]);
            acc[r][1] = fma2(ap[r], wd[1], acc[r][1]);
            acc[r][2] = fma2(ap[r], wd[2], acc[r][2]);
            acc[r][3] = fma2(ap[r], wd[3], acc[r][3]);
        }
    }

    #pragma unroll
    for (int rp = 0; rp < 8; ++rp) {
        float2 a0 = unpack2(acc[rp][0]);
        float2 a1 = unpack2(acc[rp][1]);
        float2 a2 = unpack2(acc[rp][2]);
        float2 a3 = unpack2(acc[rp][3]);
        #pragma unroll
        for (int h = 0; h < 2; ++h) {
            int e  = e0 + row0 + rp * 2 + h;
            int sn = __ldg(&src[e]);
            int dn = __ldg(&dst[e]);
            float4 uu = *reinterpret_cast<const float4*>(&u[(size_t)sn * 128 + col0]);
            float m0 = fmaxf(uu.x + (h ? a0.y : a0.x), 0.f);
            float m1 = fmaxf(uu.y + (h ? a1.y : a1.x), 0.f);
            float m2 = fmaxf(uu.z + (h ? a2.y : a2.x), 0.f);
            float m3 = fmaxf(uu.w + (h ? a3.y : a3.x), 0.f);
            float* sp = &s[(size_t)dn * 128 + col0];
            asm volatile("red.global.add.v4.f32 [%0], {%1, %2, %3, %4};"
                         :: "l"(sp), "f"(m0), "f"(m1), "f"(m2), "f"(m3) : "memory");
        }
    }
}

// ---------------- edge predictor: 4 edges per warp ----------------
__global__ void __launch_bounds__(256)
k_pred(const int* __restrict__ src, const int* __restrict__ dst,
       const float* __restrict__ p, const float* __restrict__ q,
       const float* __restrict__ W2, const float* __restrict__ b2,
       float* __restrict__ out)
{
    const int wid   = threadIdx.x >> 5;
    const int lane  = threadIdx.x & 31;
    const int ebase = (blockIdx.x * 8 + wid) * 4;      // exact: E = 50000*32

    float2 w2[4];
    #pragma unroll
    for (int t = 0; t < 4; ++t)
        w2[t] = reinterpret_cast<const float2*>(W2)[lane * 4 + t];

    float s0[4], s1[4];
    #pragma unroll
    for (int j = 0; j < 4; ++j) {
        int e  = ebase + j;
        int sn = src[e];
        int dn = dst[e];
        float4 pp = *reinterpret_cast<const float4*>(&p[(size_t)sn * 128 + lane * 4]);
        float4 qq = *reinterpret_cast<const float4*>(&q[(size_t)dn * 128 + lane * 4]);
        float h0 = fmaxf(pp.x + qq.x, 0.f);
        float h1 = fmaxf(pp.y + qq.y, 0.f);
        float h2 = fmaxf(pp.z + qq.z, 0.f);
        float h3 = fmaxf(pp.w + qq.w, 0.f);
        s0[j] = h0 * w2[0].x + h1 * w2[1].x + h2 * w2[2].x + h3 * w2[3].x;
        s1[j] = h0 * w2[0].y + h1 * w2[1].y + h2 * w2[2].y + h3 * w2[3].y;
    }

    #pragma unroll
    for (int off = 16; off > 0; off >>= 1) {
        #pragma unroll
        for (int j = 0; j < 4; ++j) {
            s0[j] += __shfl_xor_sync(0xffffffffu, s0[j], off);
            s1[j] += __shfl_xor_sync(0xffffffffu, s1[j], off);
        }
    }
    if (lane == 0) {
        #pragma unroll
        for (int j = 0; j < 4; ++j) {
            out[2 * (size_t)(ebase + j)]     = s0[j] + b2[0];
            out[2 * (size_t)(ebase + j) + 1] = s1[j] + b2[1];
        }
    }
}

// ---------------- launch ----------------
extern "C" void kernel_launch(void* const* d_in, const int* in_sizes, int n_in,
                              void* d_out, int out_size)
{
    const float* nfeats = (const float*)d_in[0];
    const float* efeats = (const float*)d_in[1];
    const int*   src    = (const int*)  d_in[2];
    const int*   dst    = (const int*)  d_in[3];
    const float* Wm1 = (const float*)d_in[4];  const float* bm1 = (const float*)d_in[5];
    const float* Wa1 = (const float*)d_in[6];  const float* ba1 = (const float*)d_in[7];
    const float* Wm2 = (const float*)d_in[8];  const float* bm2 = (const float*)d_in[9];
    const float* Wa2 = (const float*)d_in[10]; const float* ba2 = (const float*)d_in[11];
    const float* W1  = (const float*)d_in[12]; const float* b1  = (const float*)d_in[13];
    const float* W2  = (const float*)d_in[14]; const float* b2  = (const float*)d_in[15];
    float* out = (float*)d_out;

    float *u, *s, *h1, *h2, *p, *q;
    cudaGetSymbolAddress((void**)&u,  g_u);
    cudaGetSymbolAddress((void**)&s,  g_s);
    cudaGetSymbolAddress((void**)&h1, g_h1);
    cudaGetSymbolAddress((void**)&h2, g_h2);
    cudaGetSymbolAddress((void**)&p,  g_p);
    cudaGetSymbolAddress((void**)&q,  g_q);

    const int NT = (NNODES + 127) / 128;      // 391 node tiles
    const int ZB = NNODES * 128 / 4 / 256;    // 6250 zero blocks (exact)
    const int EB = NEDGES / 128;              // 12500 edge-gemm blocks (exact)
    const int CB = NEDGES / 256;              // 6250 count blocks (exact)

    // Order: k_edge is launch index 3 (ncu capture slot).
    k_init<<<ZB, 256>>>(s);                                                // 0
    k_count<<<CB, 256>>>(dst);                                             // 1
    k_gemm<<<PGRID, 256>>>(nfeats, 64, nullptr, 0, 0, Wm1, bm1, u, 0, NT); // 2
    k_edge<<<EB, 256>>>(efeats, src, dst, Wm1 + 64 * 128, u, s);           // 3 (captured)
    k_inv<<<(NNODES + 255) / 256, 256>>>();                                // 4

    // apply1 -> h1, then chained u2 = h1 @ Wm2_top + bm2
    k_chain<<<PGRID, 256>>>(nfeats, 64, s, 128, 1, Wa1, ba1, h1,
                            Wm2, bm2, u, nullptr, nullptr, NT);            // 5
    k_zero_f4<<<ZB, 256>>>(s);                                             // 6
    k_edge<<<EB, 256>>>(efeats, src, dst, Wm2 + 128 * 128, u, s);          // 7

    // apply2 -> h2, then chained p = h2@W1_top + b1, q = h2@W1_bot
    k_chain<<<PGRID, 256>>>(h1, 128, s, 128, 1, Wa2, ba2, h2,
                            W1, b1, p, W1 + 128 * 128, q, NT);             // 8
    k_pred<<<NEDGES / 32, 256>>>(src, dst, p, q, W2, b2, out);             // 9
}